// round 1
// baseline (speedup 1.0000x reference)
#include <cuda_runtime.h>
#include <math.h>

#define NTOT 2048          // B*N
#define NPER 512           // N per batch
#define KSEL 20

// scratch: [g][0..255] = x_l row, [g][256..511] = x_r row
__device__ float g_xlxr[NTOT * 512];
__device__ float g_L[NTOT];   // 0.6 * sum_d att_d * xl[g][d]
__device__ float g_R[NTOT];   // 0.6 * sum_d att_d * xr[g][d]

// ---------------------------------------------------------------------------
// Kernel 1: fused projection GEMM. C[2048][512] = X[2048][256] * Wcat^T + bias
// 64x64 tile, BK=16, 4x4 per thread, 256 threads.
// ---------------------------------------------------------------------------
__global__ __launch_bounds__(256) void proj_kernel(
    const float* __restrict__ x,
    const float* __restrict__ Wl, const float* __restrict__ bl,
    const float* __restrict__ Wr, const float* __restrict__ br)
{
    __shared__ float As[16 * 64];
    __shared__ float Bs[16 * 64];
    const int tid = threadIdx.x;
    const int tx = tid & 15, ty = tid >> 4;
    const int g0 = blockIdx.x * 64;
    const int n0 = blockIdx.y * 64;
    const float* W    = (n0 < 256) ? Wl : Wr;
    const float* bias = (n0 < 256) ? bl : br;
    const int nw0 = (n0 < 256) ? n0 : n0 - 256;

    const int lm = tid >> 2;         // 0..63
    const int lk = (tid & 3) << 2;   // 0,4,8,12

    float acc[4][4];
#pragma unroll
    for (int i = 0; i < 4; ++i)
#pragma unroll
        for (int j = 0; j < 4; ++j) acc[i][j] = 0.f;

    for (int kt = 0; kt < 256; kt += 16) {
        float4 av = *(const float4*)&x[(g0 + lm) * 256 + kt + lk];
        float4 bv = *(const float4*)&W[(nw0 + lm) * 256 + kt + lk];
        __syncthreads();
        As[(lk + 0) * 64 + lm] = av.x; As[(lk + 1) * 64 + lm] = av.y;
        As[(lk + 2) * 64 + lm] = av.z; As[(lk + 3) * 64 + lm] = av.w;
        Bs[(lk + 0) * 64 + lm] = bv.x; Bs[(lk + 1) * 64 + lm] = bv.y;
        Bs[(lk + 2) * 64 + lm] = bv.z; Bs[(lk + 3) * 64 + lm] = bv.w;
        __syncthreads();
#pragma unroll
        for (int k = 0; k < 16; ++k) {
            float4 a = *(const float4*)&As[k * 64 + ty * 4];
            float4 b = *(const float4*)&Bs[k * 64 + tx * 4];
            acc[0][0] = fmaf(a.x, b.x, acc[0][0]);
            acc[0][1] = fmaf(a.x, b.y, acc[0][1]);
            acc[0][2] = fmaf(a.x, b.z, acc[0][2]);
            acc[0][3] = fmaf(a.x, b.w, acc[0][3]);
            acc[1][0] = fmaf(a.y, b.x, acc[1][0]);
            acc[1][1] = fmaf(a.y, b.y, acc[1][1]);
            acc[1][2] = fmaf(a.y, b.z, acc[1][2]);
            acc[1][3] = fmaf(a.y, b.w, acc[1][3]);
            acc[2][0] = fmaf(a.z, b.x, acc[2][0]);
            acc[2][1] = fmaf(a.z, b.y, acc[2][1]);
            acc[2][2] = fmaf(a.z, b.z, acc[2][2]);
            acc[2][3] = fmaf(a.z, b.w, acc[2][3]);
            acc[3][0] = fmaf(a.w, b.x, acc[3][0]);
            acc[3][1] = fmaf(a.w, b.y, acc[3][1]);
            acc[3][2] = fmaf(a.w, b.z, acc[3][2]);
            acc[3][3] = fmaf(a.w, b.w, acc[3][3]);
        }
    }
#pragma unroll
    for (int i = 0; i < 4; ++i) {
        const int row = g0 + ty * 4 + i;
        float4 o;
        o.x = acc[i][0] + bias[nw0 + tx * 4 + 0];
        o.y = acc[i][1] + bias[nw0 + tx * 4 + 1];
        o.z = acc[i][2] + bias[nw0 + tx * 4 + 2];
        o.w = acc[i][3] + bias[nw0 + tx * 4 + 3];
        *(float4*)&g_xlxr[row * 512 + n0 + tx * 4] = o;
    }
}

// ---------------------------------------------------------------------------
// Kernel 2: L[g] = 0.6*sum_d att_d*xl[g][d], R[g] = 0.6*sum_d att_d*xr[g][d]
// ---------------------------------------------------------------------------
__global__ __launch_bounds__(256) void lr_kernel(const float* __restrict__ att)
{
    __shared__ float sl[8], sr[8];
    const int g = blockIdx.x, t = threadIdx.x;
    const float a = att[t];
    float vl = g_xlxr[g * 512 + t] * a;
    float vr = g_xlxr[g * 512 + 256 + t] * a;
#pragma unroll
    for (int o = 16; o; o >>= 1) {
        vl += __shfl_xor_sync(0xffffffffu, vl, o);
        vr += __shfl_xor_sync(0xffffffffu, vr, o);
    }
    if ((t & 31) == 0) { sl[t >> 5] = vl; sr[t >> 5] = vr; }
    __syncthreads();
    if (t == 0) {
        float L = 0.f, R = 0.f;
#pragma unroll
        for (int q = 0; q < 8; ++q) { L += sl[q]; R += sr[q]; }
        g_L[g] = 0.6f * L;
        g_R[g] = 0.6f * R;
    }
}

// ---------------------------------------------------------------------------
// Kernel 3: pairwise |a+b| attention, per-row top-20 + softmax, write outputs.
// Block = 16 i-rows of one batch, 256 threads (8 warps, 2 pairs/thread).
// ---------------------------------------------------------------------------
#define XR_STRIDE 260
// smem floats: xl 4096, xr 32*260=8320, alpha 8192, ws 256, Ls 16, topv 320, topi 320
#define PAIR_SMEM_BYTES ((4096 + 8320 + 8192 + 256 + 16 + 320 + 320) * 4)

__global__ __launch_bounds__(256) void pair_kernel(const float* __restrict__ att,
                                                   float* __restrict__ out)
{
    extern __shared__ float sh[];
    float* xl    = sh;                    // [16][256]
    float* xr    = xl + 16 * 256;         // [32][260]
    float* alpha = xr + 32 * XR_STRIDE;   // [16][512]
    float* ws    = alpha + 16 * 512;      // [256]
    float* Ls    = ws + 256;              // [16]
    float* topv  = Ls + 16;               // [16][20]
    int*   topi  = (int*)(topv + 16 * 20);// [16][20]

    const int tid = threadIdx.x;
    const int g0 = blockIdx.x * 16;
    const int b512 = g0 & ~511;           // batch base (g0/512)*512

    ws[tid] = 0.4f * att[tid];
#pragma unroll
    for (int q = 0; q < 4; ++q) {
        const int idx = tid + q * 256;    // float4 index 0..1023
        const int row = idx >> 6;
        const int c4 = idx & 63;
        *(float4*)&xl[row * 256 + c4 * 4] =
            *(const float4*)&g_xlxr[(g0 + row) * 512 + c4 * 4];
    }
    if (tid < 16) Ls[tid] = g_L[g0 + tid];

    const int w = tid >> 5, l = tid & 31;
    const int i0 = w * 2, i1 = w * 2 + 1;
    const float* xl0 = &xl[i0 * 256];
    const float* xl1 = &xl[i1 * 256];

    for (int jt = 0; jt < 512; jt += 32) {
        __syncthreads();                  // prev tile fully consumed (also covers init loads)
        {
            const int row = tid >> 3;     // 0..31
            const int c8 = tid & 7;
            const float4* src = (const float4*)&g_xlxr[(b512 + jt + row) * 512 + 256];
#pragma unroll
            for (int q = 0; q < 8; ++q) {
                const int c4 = c8 + q * 8;
                *(float4*)&xr[row * XR_STRIDE + c4 * 4] = src[c4];
            }
        }
        __syncthreads();

        float acc0 = 0.f, acc1 = 0.f;
        const float* xrl = &xr[l * XR_STRIDE];
#pragma unroll 4
        for (int d4 = 0; d4 < 64; ++d4) {
            const float4 r  = *(const float4*)&xrl[d4 * 4];
            const float4 a0 = *(const float4*)&xl0[d4 * 4];
            const float4 a1 = *(const float4*)&xl1[d4 * 4];
            const float4 wv = *(const float4*)&ws[d4 * 4];
            float t;
            t = a0.x + r.x; acc0 = fmaf(wv.x, fabsf(t), acc0);
            t = a0.y + r.y; acc0 = fmaf(wv.y, fabsf(t), acc0);
            t = a0.z + r.z; acc0 = fmaf(wv.z, fabsf(t), acc0);
            t = a0.w + r.w; acc0 = fmaf(wv.w, fabsf(t), acc0);
            t = a1.x + r.x; acc1 = fmaf(wv.x, fabsf(t), acc1);
            t = a1.y + r.y; acc1 = fmaf(wv.y, fabsf(t), acc1);
            t = a1.z + r.z; acc1 = fmaf(wv.z, fabsf(t), acc1);
            t = a1.w + r.w; acc1 = fmaf(wv.w, fabsf(t), acc1);
        }
        const float Rj = g_R[b512 + jt + l];
        const float L0 = Ls[i0], L1 = Ls[i1];
        alpha[i0 * 512 + jt + l] = L0 + Rj + acc0;
        alpha[i1 * 512 + jt + l] = L1 + Rj + acc1;
    }
    __syncthreads();

    // ---- top-20 per row: warp w handles rows 2w, 2w+1 ----
#pragma unroll
    for (int p = 0; p < 2; ++p) {
        const int r = w * 2 + p;
        float* arow = &alpha[r * 512];
        for (int kk = 0; kk < KSEL; ++kk) {
            float bv = -INFINITY; int bi = 0;
#pragma unroll
            for (int t8 = 0; t8 < 16; ++t8) {
                const int j = l + t8 * 32;
                const float v = arow[j];
                if (v > bv) { bv = v; bi = j; }   // strict > keeps lowest index
            }
#pragma unroll
            for (int off = 16; off; off >>= 1) {
                const float ov = __shfl_xor_sync(0xffffffffu, bv, off);
                const int   oi = __shfl_xor_sync(0xffffffffu, bi, off);
                if (ov > bv || (ov == bv && oi < bi)) { bv = ov; bi = oi; }
            }
            if (l == 0) {
                topv[r * KSEL + kk] = bv;
                topi[r * KSEL + kk] = bi;
                arow[bi] = -INFINITY;
            }
            __syncwarp();
        }
        // softmax over the 20 selected (sorted desc; topv[r][0] is the max)
        const float m = topv[r * KSEL];
        float e = 0.f; int myi = 0;
        if (l < KSEL) {
            e = expf(topv[r * KSEL + l] - m);
            myi = topi[r * KSEL + l];
        }
        float s = e;
#pragma unroll
        for (int off = 16; off; off >>= 1) s += __shfl_xor_sync(0xffffffffu, s, off);
        if (l < KSEL) {
            const int g = g0 + r;
            const int base = g * KSEL + l;
            out[base]                     = (float)g;             // index_i
            out[NTOT * KSEL + base]       = (float)(b512 + myi);  // index_j
            out[2 * NTOT * KSEL + base]   = e / s;                // attention
        }
    }
}

// ---------------------------------------------------------------------------
extern "C" void kernel_launch(void* const* d_in, const int* in_sizes, int n_in,
                              void* d_out, int out_size)
{
    const float* x   = (const float*)d_in[0];
    // d_in[1] = edge_index (unused), d_in[2] = batch (unused)
    const float* Wl  = (const float*)d_in[3];
    const float* bl  = (const float*)d_in[4];
    const float* Wr  = (const float*)d_in[5];
    const float* br  = (const float*)d_in[6];
    const float* att = (const float*)d_in[7];
    float* out = (float*)d_out;

    proj_kernel<<<dim3(32, 8), 256>>>(x, Wl, bl, Wr, br);
    lr_kernel<<<NTOT, 256>>>(att);
    cudaFuncSetAttribute(pair_kernel, cudaFuncAttributeMaxDynamicSharedMemorySize,
                         PAIR_SMEM_BYTES);
    pair_kernel<<<128, 256, PAIR_SMEM_BYTES>>>(att, out);
}

// round 2
// speedup vs baseline: 1.1384x; 1.1384x over previous
#include <cuda_runtime.h>
#include <math.h>

#define NTOT 2048          // B*N
#define NPER 512           // N per batch
#define KSEL 20

// scratch: [g][0..255] = x_l row, [g][256..511] = x_r row
__device__ float g_xlxr[NTOT * 512];
__device__ float g_L[NTOT];   // 0.6 * sum_d att_d * xl[g][d]
__device__ float g_R[NTOT];   // 0.6 * sum_d att_d * xr[g][d]

// ---------------- packed f32x2 helpers ----------------
__device__ __forceinline__ double fma2(double a, double b, double c) {
    double d;
    asm("fma.rn.f32x2 %0, %1, %2, %3;" : "=d"(d) : "d"(a), "d"(b), "d"(c));
    return d;
}
__device__ __forceinline__ double add2(double a, double b) {
    double d;
    asm("add.rn.f32x2 %0, %1, %2;" : "=d"(d) : "d"(a), "d"(b));
    return d;
}
__device__ __forceinline__ double abs2(double a) {
    return __longlong_as_double(__double_as_longlong(a) & 0x7fffffff7fffffffULL);
}
__device__ __forceinline__ double dup2(float v) {
    double d;
    asm("mov.b64 %0, {%1, %1};" : "=d"(d) : "f"(v));
    return d;
}
__device__ __forceinline__ float2 unpack2(double a) {
    float2 f;
    asm("mov.b64 {%0, %1}, %2;" : "=f"(f.x), "=f"(f.y) : "d"(a));
    return f;
}

// ---------------------------------------------------------------------------
// Kernel 1: fused projection GEMM. C[2048][512] = X[2048][256] * Wcat^T + bias
// 64x64 tile, BK=16, packed f32x2 over N (A duplicated in smem), 256 threads,
// register prefetch of the next k-tile overlapping compute.
// ---------------------------------------------------------------------------
__global__ __launch_bounds__(256) void proj_kernel(
    const float* __restrict__ x,
    const float* __restrict__ Wl, const float* __restrict__ bl,
    const float* __restrict__ Wr, const float* __restrict__ br)
{
    __shared__ __align__(16) float As2[16 * 132];  // [k][2m] duplicated pairs
    __shared__ __align__(16) float Bs[16 * 68];    // [k][n]
    const int tid = threadIdx.x;
    const int tx = tid & 15, ty = tid >> 4;
    const int g0 = blockIdx.x * 64;
    const int n0 = blockIdx.y * 64;
    const float* W    = (n0 < 256) ? Wl : Wr;
    const float* bias = (n0 < 256) ? bl : br;
    const int nw0 = (n0 < 256) ? n0 : n0 - 256;

    const int lm = tid >> 2;         // 0..63
    const int lk = (tid & 3) << 2;   // 0,4,8,12

    double acc[4][2];
#pragma unroll
    for (int i = 0; i < 4; ++i) { acc[i][0] = 0.0; acc[i][1] = 0.0; }

    const float* xp = &x[(g0 + lm) * 256 + lk];
    const float* wp = &W[(nw0 + lm) * 256 + lk];
    float4 av = *(const float4*)xp;
    float4 bv = *(const float4*)wp;

    for (int kt = 0; kt < 256; kt += 16) {
        __syncthreads();
        // store current tile (A duplicated as (v,v) pairs)
        *(double*)&As2[(lk + 0) * 132 + 2 * lm] = dup2(av.x);
        *(double*)&As2[(lk + 1) * 132 + 2 * lm] = dup2(av.y);
        *(double*)&As2[(lk + 2) * 132 + 2 * lm] = dup2(av.z);
        *(double*)&As2[(lk + 3) * 132 + 2 * lm] = dup2(av.w);
        Bs[(lk + 0) * 68 + lm] = bv.x;
        Bs[(lk + 1) * 68 + lm] = bv.y;
        Bs[(lk + 2) * 68 + lm] = bv.z;
        Bs[(lk + 3) * 68 + lm] = bv.w;
        __syncthreads();
        if (kt + 16 < 256) {          // prefetch next tile, overlap with compute
            av = *(const float4*)(xp + kt + 16);
            bv = *(const float4*)(wp + kt + 16);
        }
#pragma unroll
        for (int k = 0; k < 16; ++k) {
            const double2 alo = *(const double2*)&As2[k * 132 + 8 * ty];      // rows 4ty,4ty+1 dup'd
            const double2 ahi = *(const double2*)&As2[k * 132 + 8 * ty + 4];  // rows 4ty+2,4ty+3
            const double2 b2  = *(const double2*)&Bs[k * 68 + 4 * tx];        // (b0,b1),(b2,b3)
            acc[0][0] = fma2(alo.x, b2.x, acc[0][0]);
            acc[0][1] = fma2(alo.x, b2.y, acc[0][1]);
            acc[1][0] = fma2(alo.y, b2.x, acc[1][0]);
            acc[1][1] = fma2(alo.y, b2.y, acc[1][1]);
            acc[2][0] = fma2(ahi.x, b2.x, acc[2][0]);
            acc[2][1] = fma2(ahi.x, b2.y, acc[2][1]);
            acc[3][0] = fma2(ahi.y, b2.x, acc[3][0]);
            acc[3][1] = fma2(ahi.y, b2.y, acc[3][1]);
        }
    }
#pragma unroll
    for (int i = 0; i < 4; ++i) {
        const int row = g0 + ty * 4 + i;
        const float2 p0 = unpack2(acc[i][0]);
        const float2 p1 = unpack2(acc[i][1]);
        float4 o;
        o.x = p0.x + bias[nw0 + tx * 4 + 0];
        o.y = p0.y + bias[nw0 + tx * 4 + 1];
        o.z = p1.x + bias[nw0 + tx * 4 + 2];
        o.w = p1.y + bias[nw0 + tx * 4 + 3];
        *(float4*)&g_xlxr[row * 512 + n0 + tx * 4] = o;
    }
}

// ---------------------------------------------------------------------------
// Kernel 2: L[g] = 0.6*sum_d att_d*xl[g][d], R[g] = 0.6*sum_d att_d*xr[g][d]
// ---------------------------------------------------------------------------
__global__ __launch_bounds__(256) void lr_kernel(const float* __restrict__ att)
{
    __shared__ float sl[8], sr[8];
    const int g = blockIdx.x, t = threadIdx.x;
    const float a = att[t];
    float vl = g_xlxr[g * 512 + t] * a;
    float vr = g_xlxr[g * 512 + 256 + t] * a;
#pragma unroll
    for (int o = 16; o; o >>= 1) {
        vl += __shfl_xor_sync(0xffffffffu, vl, o);
        vr += __shfl_xor_sync(0xffffffffu, vr, o);
    }
    if ((t & 31) == 0) { sl[t >> 5] = vl; sr[t >> 5] = vr; }
    __syncthreads();
    if (t == 0) {
        float L = 0.f, R = 0.f;
#pragma unroll
        for (int q = 0; q < 8; ++q) { L += sl[q]; R += sr[q]; }
        g_L[g] = 0.6f * L;
        g_R[g] = 0.6f * R;
    }
}

// ---------------------------------------------------------------------------
// Kernel 3: pairwise sum_d w_d*|xl_id + xr_jd|, top-20 + softmax per row.
// Block = 16 i-rows, 256 threads. Warp w: rows 4*(w&3).., j-half (w>>2).
// Packed f32x2 math; xr tiles (64 j-rows) double-buffered via cp.async.
// ---------------------------------------------------------------------------
#define XR_STRIDE 260
#define XR_TILE   (64 * XR_STRIDE)   // floats per tile
// floats: xl 4096, ws 256, Rs 512, Ls 16, topv 320, topi 320, alpha 8192, xr 2*16640
#define PAIR_FLOATS (4096 + 256 + 512 + 16 + 320 + 320 + 8192 + 2 * XR_TILE)
#define PAIR_SMEM_BYTES (PAIR_FLOATS * 4)

__device__ __forceinline__ void cp16(void* dst, const void* src) {
    unsigned u = (unsigned)__cvta_generic_to_shared(dst);
    asm volatile("cp.async.cg.shared.global [%0], [%1], 16;" :: "r"(u), "l"(src) : "memory");
}

__global__ __launch_bounds__(256) void pair_kernel(const float* __restrict__ att,
                                                   float* __restrict__ out)
{
    extern __shared__ float sh[];
    float* xl    = sh;                    // [16][256]
    float* ws    = xl + 16 * 256;         // [256]
    float* Rs    = ws + 256;              // [512]
    float* Ls    = Rs + 512;              // [16]
    float* topv  = Ls + 16;               // [16][20]
    int*   topi  = (int*)(topv + 320);    // [16][20]
    float* alpha = (float*)(topi + 320);  // [16][512]
    float* xrbuf = alpha + 16 * 512;      // [2][64][260]

    const int tid = threadIdx.x;
    const int g0 = blockIdx.x * 16;
    const int b512 = g0 & ~511;           // batch base

    ws[tid] = 0.4f * att[tid];
    Rs[tid]       = g_R[b512 + tid];
    Rs[tid + 256] = g_R[b512 + 256 + tid];
    if (tid < 16) Ls[tid] = g_L[g0 + tid];
#pragma unroll
    for (int q = 0; q < 4; ++q) {
        const int idx = tid + q * 256;    // float4 index 0..1023
        const int row = idx >> 6;
        const int c4 = idx & 63;
        *(float4*)&xl[row * 256 + c4 * 4] =
            *(const float4*)&g_xlxr[(g0 + row) * 512 + c4 * 4];
    }

    const int w = tid >> 5, l = tid & 31;
    const int half = w >> 2;              // j sub-tile (0/1)
    const int r0 = (w & 3) * 4;           // first of this warp's 4 rows
    const int jr = half * 32 + l;         // row within the 64-row xr tile

    // prologue: async-load xr tile 0 into buffer 0
    {
        float* dst = xrbuf;
#pragma unroll
        for (int q = 0; q < 16; ++q) {
            const int cid = tid + q * 256;
            const int row = cid >> 6, c = cid & 63;
            cp16(dst + row * XR_STRIDE + c * 4,
                 &g_xlxr[(size_t)(b512 + row) * 512 + 256 + c * 4]);
        }
        asm volatile("cp.async.commit_group;" ::: "memory");
    }

    for (int it = 0; it < 8; ++it) {
        asm volatile("cp.async.wait_group 0;" ::: "memory");
        __syncthreads();                  // tile ready for all; prev buffer free
        if (it < 7) {
            float* dst = xrbuf + ((it + 1) & 1) * XR_TILE;
            const int jb = b512 + (it + 1) * 64;
#pragma unroll
            for (int q = 0; q < 16; ++q) {
                const int cid = tid + q * 256;
                const int row = cid >> 6, c = cid & 63;
                cp16(dst + row * XR_STRIDE + c * 4,
                     &g_xlxr[(size_t)(jb + row) * 512 + 256 + c * 4]);
            }
            asm volatile("cp.async.commit_group;" ::: "memory");
        }

        const float* xrl = xrbuf + (it & 1) * XR_TILE + jr * XR_STRIDE;
        const float* xl0 = xl + (r0 + 0) * 256;
        const float* xl1 = xl + (r0 + 1) * 256;
        const float* xl2 = xl + (r0 + 2) * 256;
        const float* xl3 = xl + (r0 + 3) * 256;

        double c00 = 0, c01 = 0, c10 = 0, c11 = 0;
        double c20 = 0, c21 = 0, c30 = 0, c31 = 0;
#pragma unroll 8
        for (int d4 = 0; d4 < 64; ++d4) {
            const double2 r2 = *(const double2*)(xrl + d4 * 4);
            const double2 w2 = *(const double2*)(ws + d4 * 4);
            double2 a; double t0, t1;
            a = *(const double2*)(xl0 + d4 * 4);
            t0 = add2(a.x, r2.x); t1 = add2(a.y, r2.y);
            c00 = fma2(w2.x, abs2(t0), c00); c01 = fma2(w2.y, abs2(t1), c01);
            a = *(const double2*)(xl1 + d4 * 4);
            t0 = add2(a.x, r2.x); t1 = add2(a.y, r2.y);
            c10 = fma2(w2.x, abs2(t0), c10); c11 = fma2(w2.y, abs2(t1), c11);
            a = *(const double2*)(xl2 + d4 * 4);
            t0 = add2(a.x, r2.x); t1 = add2(a.y, r2.y);
            c20 = fma2(w2.x, abs2(t0), c20); c21 = fma2(w2.y, abs2(t1), c21);
            a = *(const double2*)(xl3 + d4 * 4);
            t0 = add2(a.x, r2.x); t1 = add2(a.y, r2.y);
            c30 = fma2(w2.x, abs2(t0), c30); c31 = fma2(w2.y, abs2(t1), c31);
        }
        const int j = it * 64 + jr;       // column within batch
        const float Rj = Rs[j];
        float2 p, q2; float s0, s1;
        p = unpack2(c00); q2 = unpack2(c01);
        s0 = p.x + p.y; s1 = q2.x + q2.y;
        alpha[(r0 + 0) * 512 + j] = Ls[r0 + 0] + Rj + (s0 + s1);
        p = unpack2(c10); q2 = unpack2(c11);
        s0 = p.x + p.y; s1 = q2.x + q2.y;
        alpha[(r0 + 1) * 512 + j] = Ls[r0 + 1] + Rj + (s0 + s1);
        p = unpack2(c20); q2 = unpack2(c21);
        s0 = p.x + p.y; s1 = q2.x + q2.y;
        alpha[(r0 + 2) * 512 + j] = Ls[r0 + 2] + Rj + (s0 + s1);
        p = unpack2(c30); q2 = unpack2(c31);
        s0 = p.x + p.y; s1 = q2.x + q2.y;
        alpha[(r0 + 3) * 512 + j] = Ls[r0 + 3] + Rj + (s0 + s1);
    }
    __syncthreads();

    // ---- top-20 per row: warp w handles rows 2w, 2w+1 ----
#pragma unroll
    for (int p = 0; p < 2; ++p) {
        const int r = w * 2 + p;
        float* arow = &alpha[r * 512];
        for (int kk = 0; kk < KSEL; ++kk) {
            float bv = -INFINITY; int bi = 0;
#pragma unroll
            for (int t8 = 0; t8 < 16; ++t8) {
                const int j = l + t8 * 32;
                const float v = arow[j];
                if (v > bv) { bv = v; bi = j; }   // strict > keeps lowest index
            }
#pragma unroll
            for (int off = 16; off; off >>= 1) {
                const float ov = __shfl_xor_sync(0xffffffffu, bv, off);
                const int   oi = __shfl_xor_sync(0xffffffffu, bi, off);
                if (ov > bv || (ov == bv && oi < bi)) { bv = ov; bi = oi; }
            }
            if (l == 0) {
                topv[r * KSEL + kk] = bv;
                topi[r * KSEL + kk] = bi;
                arow[bi] = -INFINITY;
            }
            __syncwarp();
        }
        // softmax over the 20 selected (sorted desc; topv[r][0] is the max)
        const float m = topv[r * KSEL];
        float e = 0.f; int myi = 0;
        if (l < KSEL) {
            e = expf(topv[r * KSEL + l] - m);
            myi = topi[r * KSEL + l];
        }
        float s = e;
#pragma unroll
        for (int off = 16; off; off >>= 1) s += __shfl_xor_sync(0xffffffffu, s, off);
        if (l < KSEL) {
            const int g = g0 + r;
            const int base = g * KSEL + l;
            out[base]                     = (float)g;             // index_i
            out[NTOT * KSEL + base]       = (float)(b512 + myi);  // index_j
            out[2 * NTOT * KSEL + base]   = e / s;                // attention
        }
    }
}

// ---------------------------------------------------------------------------
extern "C" void kernel_launch(void* const* d_in, const int* in_sizes, int n_in,
                              void* d_out, int out_size)
{
    const float* x   = (const float*)d_in[0];
    // d_in[1] = edge_index (unused), d_in[2] = batch (unused)
    const float* Wl  = (const float*)d_in[3];
    const float* bl  = (const float*)d_in[4];
    const float* Wr  = (const float*)d_in[5];
    const float* br  = (const float*)d_in[6];
    const float* att = (const float*)d_in[7];
    float* out = (float*)d_out;

    proj_kernel<<<dim3(32, 8), 256>>>(x, Wl, bl, Wr, br);
    lr_kernel<<<NTOT, 256>>>(att);
    cudaFuncSetAttribute(pair_kernel, cudaFuncAttributeMaxDynamicSharedMemorySize,
                         PAIR_SMEM_BYTES);
    pair_kernel<<<128, 256, PAIR_SMEM_BYTES>>>(att, out);
}

// round 3
// speedup vs baseline: 1.2051x; 1.0585x over previous
#include <cuda_runtime.h>
#include <math.h>

#define NTOT 2048          // B*N
#define KSEL 20

__device__ float  g_part[2 * NTOT * 512]; // K-split partial GEMM results
__device__ float  g_xlxr[NTOT * 512];     // [g][0:256)=xl, [256:512)=xr
__device__ float2 g_xrP[4 * 128 * 512];   // [b][d2][j] = (xr[j][2d2], xr[j][2d2+1])
__device__ float  g_alpha[NTOT * 512];
__device__ float  g_L[NTOT];
__device__ float  g_R[NTOT];

// ---------------- packed f32x2 helpers ----------------
__device__ __forceinline__ double fma2(double a, double b, double c) {
    double d;
    asm("fma.rn.f32x2 %0, %1, %2, %3;" : "=d"(d) : "d"(a), "d"(b), "d"(c));
    return d;
}
__device__ __forceinline__ double add2(double a, double b) {
    double d;
    asm("add.rn.f32x2 %0, %1, %2;" : "=d"(d) : "d"(a), "d"(b));
    return d;
}
__device__ __forceinline__ double abs2(double a) {
    return __longlong_as_double(__double_as_longlong(a) & 0x7fffffff7fffffffULL);
}
__device__ __forceinline__ double dup2(float v) {
    double d;
    asm("mov.b64 %0, {%1, %1};" : "=d"(d) : "f"(v));
    return d;
}
__device__ __forceinline__ float2 unpack2(double a) {
    float2 f;
    asm("mov.b64 {%0, %1}, %2;" : "=f"(f.x), "=f"(f.y) : "d"(a));
    return f;
}

// ---------------------------------------------------------------------------
// Kernel 1: K-split projection GEMM. 64x64 tile, BK=16, 8 k-tiles per block,
// double-buffered smem (1 sync/tile), LDG 2 tiles ahead. grid (32, 8, 2).
// Writes partials to g_part[kh]. Bias added by kh==0 only.
// ---------------------------------------------------------------------------
__global__ __launch_bounds__(256) void proj_kernel(
    const float* __restrict__ x,
    const float* __restrict__ Wl, const float* __restrict__ bl,
    const float* __restrict__ Wr, const float* __restrict__ br)
{
    __shared__ __align__(16) float As2[2][16 * 132];  // [stage][k][2m] dup pairs
    __shared__ __align__(16) float Bs[2][16 * 68];    // [stage][k][n]
    const int tid = threadIdx.x;
    const int tx = tid & 15, ty = tid >> 4;
    const int g0 = blockIdx.x * 64;
    const int n0 = blockIdx.y * 64;
    const int kh = blockIdx.z;                         // K half
    const float* W    = (n0 < 256) ? Wl : Wr;
    const float* bias = (n0 < 256) ? bl : br;
    const int nw0 = (n0 < 256) ? n0 : n0 - 256;

    const int lm = tid >> 2;         // 0..63
    const int lk = (tid & 3) << 2;   // 0,4,8,12

    double acc[4][2];
#pragma unroll
    for (int i = 0; i < 4; ++i) { acc[i][0] = 0.0; acc[i][1] = 0.0; }

    const float* xp = &x[(g0 + lm) * 256 + kh * 128 + lk];
    const float* wp = &W[(nw0 + lm) * 256 + kh * 128 + lk];

    // prologue: tile0 -> stage0, then fetch tile1 into regs
    float4 av = *(const float4*)xp;
    float4 bv = *(const float4*)wp;
    {
        float* A = As2[0]; float* B = Bs[0];
        *(double*)&A[(lk + 0) * 132 + 2 * lm] = dup2(av.x);
        *(double*)&A[(lk + 1) * 132 + 2 * lm] = dup2(av.y);
        *(double*)&A[(lk + 2) * 132 + 2 * lm] = dup2(av.z);
        *(double*)&A[(lk + 3) * 132 + 2 * lm] = dup2(av.w);
        B[(lk + 0) * 68 + lm] = bv.x; B[(lk + 1) * 68 + lm] = bv.y;
        B[(lk + 2) * 68 + lm] = bv.z; B[(lk + 3) * 68 + lm] = bv.w;
    }
    av = *(const float4*)(xp + 16);
    bv = *(const float4*)(wp + 16);

#pragma unroll 1
    for (int t = 0; t < 8; ++t) {
        __syncthreads();
        if (t < 7) {
            float* A = As2[(t + 1) & 1]; float* B = Bs[(t + 1) & 1];
            *(double*)&A[(lk + 0) * 132 + 2 * lm] = dup2(av.x);
            *(double*)&A[(lk + 1) * 132 + 2 * lm] = dup2(av.y);
            *(double*)&A[(lk + 2) * 132 + 2 * lm] = dup2(av.z);
            *(double*)&A[(lk + 3) * 132 + 2 * lm] = dup2(av.w);
            B[(lk + 0) * 68 + lm] = bv.x; B[(lk + 1) * 68 + lm] = bv.y;
            B[(lk + 2) * 68 + lm] = bv.z; B[(lk + 3) * 68 + lm] = bv.w;
        }
        if (t < 6) {
            av = *(const float4*)(xp + (t + 2) * 16);
            bv = *(const float4*)(wp + (t + 2) * 16);
        }
        const float* A = As2[t & 1]; const float* B = Bs[t & 1];
#pragma unroll
        for (int k = 0; k < 16; ++k) {
            const double2 alo = *(const double2*)&A[k * 132 + 8 * ty];
            const double2 ahi = *(const double2*)&A[k * 132 + 8 * ty + 4];
            const double2 b2  = *(const double2*)&B[k * 68 + 4 * tx];
            acc[0][0] = fma2(alo.x, b2.x, acc[0][0]);
            acc[0][1] = fma2(alo.x, b2.y, acc[0][1]);
            acc[1][0] = fma2(alo.y, b2.x, acc[1][0]);
            acc[1][1] = fma2(alo.y, b2.y, acc[1][1]);
            acc[2][0] = fma2(ahi.x, b2.x, acc[2][0]);
            acc[2][1] = fma2(ahi.x, b2.y, acc[2][1]);
            acc[3][0] = fma2(ahi.y, b2.x, acc[3][0]);
            acc[3][1] = fma2(ahi.y, b2.y, acc[3][1]);
        }
    }

    float* dst = g_part + (size_t)kh * NTOT * 512;
#pragma unroll
    for (int i = 0; i < 4; ++i) {
        const int row = g0 + ty * 4 + i;
        const float2 p0 = unpack2(acc[i][0]);
        const float2 p1 = unpack2(acc[i][1]);
        float4 o;
        if (kh == 0) {
            o.x = p0.x + bias[nw0 + tx * 4 + 0];
            o.y = p0.y + bias[nw0 + tx * 4 + 1];
            o.z = p1.x + bias[nw0 + tx * 4 + 2];
            o.w = p1.y + bias[nw0 + tx * 4 + 3];
        } else {
            o.x = p0.x; o.y = p0.y; o.z = p1.x; o.w = p1.y;
        }
        *(float4*)&dst[row * 512 + n0 + tx * 4] = o;
    }
}

// ---------------------------------------------------------------------------
// Kernel 2: finalize. Per block: 32 g-rows. Sum K-partials -> g_xlxr + smem
// slab; compute L/R (att dots); emit d-major pair-packed transpose g_xrP.
// ---------------------------------------------------------------------------
#define SLAB_S 524   // float stride: 16B-aligned rows, low smem conflicts
#define FIN_SMEM ((32 * SLAB_S + 256) * 4)

__global__ __launch_bounds__(256) void finalize_kernel(const float* __restrict__ att)
{
    extern __shared__ float sh[];
    float* slab  = sh;                 // [32][SLAB_S]
    float* att_s = sh + 32 * SLAB_S;   // [256]
    const int tid = threadIdx.x;
    const int g0 = blockIdx.x * 32;
    const int b = g0 >> 9;
    const int j0b = g0 & 511;

    att_s[tid] = att[tid];
    // phase 1: sum partials, write g_xlxr, stage slab
#pragma unroll
    for (int p = 0; p < 16; ++p) {
        const int idx = p * 256 + tid;    // float4 id over 32*128
        const int row = idx >> 7, c4 = idx & 127;
        const size_t ga = (size_t)(g0 + row) * 512 + c4 * 4;
        float4 a = *(const float4*)&g_part[ga];
        const float4 c = *(const float4*)&g_part[(size_t)NTOT * 512 + ga];
        a.x += c.x; a.y += c.y; a.z += c.z; a.w += c.w;
        *(float4*)&g_xlxr[ga] = a;
        *(float4*)&slab[row * SLAB_S + c4 * 4] = a;
    }
    __syncthreads();

    // phase 2: L/R dots. 64 dots (32 rows x {l,r}), warp per dot, 8 passes
    const int w = tid >> 5, l = tid & 31;
#pragma unroll
    for (int p = 0; p < 8; ++p) {
        const int id = p * 8 + w;
        const int row = id >> 1, half = id & 1;
        float s = 0.f;
#pragma unroll
        for (int q = 0; q < 8; ++q)
            s += att_s[l + 32 * q] * slab[row * SLAB_S + half * 256 + l + 32 * q];
#pragma unroll
        for (int off = 16; off; off >>= 1) s += __shfl_xor_sync(0xffffffffu, s, off);
        if (l == 0) {
            if (half) g_R[g0 + row] = 0.6f * s;
            else      g_L[g0 + row] = 0.6f * s;
        }
    }

    // phase 3: transpose xr half -> g_xrP[b][d2][j]
#pragma unroll
    for (int p = 0; p < 16; ++p) {
        const int idx = p * 256 + tid;    // 0..4095
        const int d2 = idx >> 5, jl = idx & 31;
        const float2 v = *(const float2*)&slab[jl * SLAB_S + 256 + 2 * d2];
        g_xrP[((size_t)b * 128 + d2) * 512 + j0b + jl] = v;
    }
}

// ---------------------------------------------------------------------------
// Kernel 3: pairwise scores. grid (128 i-tiles, 4 j-quarters), 256 threads.
// Lane l owns column j for the whole kernel; warp group (w>>2) owns 8 i-rows.
// xr read coalesced from g_xrP (gmem), xl/ws broadcast from smem,
// accumulators in registers. Writes alpha to gmem.
// ---------------------------------------------------------------------------
__global__ __launch_bounds__(256, 3) void pair_kernel(const float* __restrict__ att)
{
    __shared__ float xl[16 * 256];
    __shared__ float ws[256];
    __shared__ float Ls[16];

    const int tid = threadIdx.x;
    const int g0 = blockIdx.x * 16;
    const int b512 = g0 & ~511;
    const int jq = blockIdx.y;

    ws[tid] = 0.4f * att[tid];
#pragma unroll
    for (int q = 0; q < 4; ++q) {
        const int idx = tid + q * 256;
        const int row = idx >> 6, c4 = idx & 63;
        *(float4*)&xl[row * 256 + c4 * 4] =
            *(const float4*)&g_xlxr[(size_t)(g0 + row) * 512 + c4 * 4];
    }
    if (tid < 16) Ls[tid] = g_L[g0 + tid];
    __syncthreads();

    const int w = tid >> 5, l = tid & 31;
    const int grp = w >> 2;            // 0/1: i-rows grp*8..grp*8+7
    const int jsl = w & 3;
    const int jj = jq * 128 + jsl * 32 + l;   // j within batch
    const float Rj = g_R[b512 + jj];
    const double* __restrict__ xrp = (const double*)g_xrP + (size_t)(b512 >> 9) * 128 * 512;

    double acc[8];
#pragma unroll
    for (int i = 0; i < 8; ++i) acc[i] = 0.0;

#pragma unroll 1
    for (int ch = 0; ch < 8; ++ch) {   // chunks of 32 d (16 d-pairs)
        double xr[16];
#pragma unroll
        for (int q = 0; q < 16; ++q)
            xr[q] = xrp[(size_t)(ch * 16 + q) * 512 + jj];
#pragma unroll
        for (int i = 0; i < 8; ++i) {
            const float* xlr = xl + (grp * 8 + i) * 256 + ch * 32;
            const float* wsr = ws + ch * 32;
            double a = acc[i];
#pragma unroll
            for (int q2 = 0; q2 < 8; ++q2) {
                const double2 av = *(const double2*)(xlr + q2 * 4);
                const double2 wv = *(const double2*)(wsr + q2 * 4);
                const double t0 = add2(av.x, xr[2 * q2]);
                const double t1 = add2(av.y, xr[2 * q2 + 1]);
                a = fma2(wv.x, abs2(t0), a);
                a = fma2(wv.y, abs2(t1), a);
            }
            acc[i] = a;
        }
    }
#pragma unroll
    for (int i = 0; i < 8; ++i) {
        const float2 p = unpack2(acc[i]);
        const int r = grp * 8 + i;
        g_alpha[(size_t)(g0 + r) * 512 + jj] = Ls[r] + Rj + (p.x + p.y);
    }
}

// ---------------------------------------------------------------------------
// Kernel 4: register-resident top-20 + softmax. Warp per row, grid 256.
// ---------------------------------------------------------------------------
__global__ __launch_bounds__(256) void topk_kernel(float* __restrict__ out)
{
    const int tid = threadIdx.x;
    const int w = tid >> 5, l = tid & 31;
    const int g = blockIdx.x * 8 + w;
    const float* __restrict__ arow = g_alpha + (size_t)g * 512;

    float v[16];
#pragma unroll
    for (int t = 0; t < 16; ++t) v[t] = arow[l + 32 * t];

    float wv = 0.f; int wj = 0;
    for (int kk = 0; kk < KSEL; ++kk) {
        float bv = -INFINITY; int bt = 0;
#pragma unroll
        for (int t = 0; t < 16; ++t)
            if (v[t] > bv) { bv = v[t]; bt = t; }   // strict > keeps lowest j
        int bj = bt * 32 + l;
#pragma unroll
        for (int off = 16; off; off >>= 1) {
            const float ov = __shfl_xor_sync(0xffffffffu, bv, off);
            const int   oj = __shfl_xor_sync(0xffffffffu, bj, off);
            if (ov > bv || (ov == bv && oj < bj)) { bv = ov; bj = oj; }
        }
        if (l == kk) { wv = bv; wj = bj; }
        const int owner = bj & 31, slot = bj >> 5;
        if (l == owner) {
#pragma unroll
            for (int t = 0; t < 16; ++t)
                if (slot == t) v[t] = -INFINITY;
        }
    }

    const float m = __shfl_sync(0xffffffffu, wv, 0);   // largest selected
    const float e = (l < KSEL) ? expf(wv - m) : 0.f;
    float s = e;
#pragma unroll
    for (int off = 16; off; off >>= 1) s += __shfl_xor_sync(0xffffffffu, s, off);
    if (l < KSEL) {
        const int base = g * KSEL + l;
        out[base]                   = (float)g;                   // index_i
        out[NTOT * KSEL + base]     = (float)((g & ~511) + wj);   // index_j
        out[2 * NTOT * KSEL + base] = e / s;                      // attention
    }
}

// ---------------------------------------------------------------------------
extern "C" void kernel_launch(void* const* d_in, const int* in_sizes, int n_in,
                              void* d_out, int out_size)
{
    const float* x   = (const float*)d_in[0];
    // d_in[1] = edge_index (unused), d_in[2] = batch (unused)
    const float* Wl  = (const float*)d_in[3];
    const float* bl  = (const float*)d_in[4];
    const float* Wr  = (const float*)d_in[5];
    const float* br  = (const float*)d_in[6];
    const float* att = (const float*)d_in[7];
    float* out = (float*)d_out;

    proj_kernel<<<dim3(32, 8, 2), 256>>>(x, Wl, bl, Wr, br);
    cudaFuncSetAttribute(finalize_kernel,
                         cudaFuncAttributeMaxDynamicSharedMemorySize, FIN_SMEM);
    finalize_kernel<<<64, 256, FIN_SMEM>>>(att);
    pair_kernel<<<dim3(128, 4), 256>>>(att);
    topk_kernel<<<256, 256>>>(out);
}